// round 1
// baseline (speedup 1.0000x reference)
#include <cuda_runtime.h>
#include <cuda_bf16.h>
#include <stdint.h>

#define N 8192
#define ISIZE 256
#define KTOP 31  // keep top (k+1) = 31 per row

// scratch: normalized embedding e  [N][ISIZE]  (8 MB, static device global — no allocs)
__device__ float g_e[N * ISIZE];

// ---------------------------------------------------------------------------
// Kernel 1: h = relu(f * w0) * w1 ; e = h / max(||h||_2, eps)
// one block (256 threads) per row
// ---------------------------------------------------------------------------
__global__ void k_normalize(const float* __restrict__ f, const float* __restrict__ w,
                            float* __restrict__ e) {
    int row = blockIdx.x;
    int t = threadIdx.x;  // 0..255 == column
    float v = f[row * ISIZE + t];
    v = fmaxf(v * w[t], 0.0f) * w[ISIZE + t];

    float s = v * v;
    #pragma unroll
    for (int o = 16; o; o >>= 1) s += __shfl_xor_sync(0xFFFFFFFFu, s, o);
    __shared__ float ws[8];
    if ((t & 31) == 0) ws[t >> 5] = s;
    __syncthreads();
    if (t < 8) {
        float x = ws[t];
        #pragma unroll
        for (int o = 4; o; o >>= 1) x += __shfl_xor_sync(0xFFu, x, o);
        if (t == 0) ws[0] = x;
    }
    __syncthreads();
    float inv = 1.0f / fmaxf(sqrtf(ws[0]), 1e-12f);
    e[row * ISIZE + t] = v * inv;
}

// ---------------------------------------------------------------------------
// Kernel 2: C = E * E^T   (fp32 SIMT tiled GEMM, 128x128 tile, K=256)
// ---------------------------------------------------------------------------
#define BM 128
#define BN 128
#define BK 16

__global__ void __launch_bounds__(256, 2) k_gemm(const float* __restrict__ E,
                                                 float* __restrict__ C) {
    __shared__ float As[BK][BM + 4];
    __shared__ float Bs[BK][BN + 4];

    int bx = blockIdx.x;  // N tile
    int by = blockIdx.y;  // M tile
    int tid = threadIdx.x;
    int tx = tid % 16;    // 0..15 -> col micro-tile
    int ty = tid / 16;    // 0..15 -> row micro-tile

    float acc[8][8];
    #pragma unroll
    for (int i = 0; i < 8; i++)
        #pragma unroll
        for (int j = 0; j < 8; j++) acc[i][j] = 0.0f;

    int lrow = tid / 4;          // 0..63
    int lcol4 = (tid % 4) * 4;   // 0,4,8,12

    const float* Abase = E + (size_t)(by * BM) * ISIZE;
    const float* Bbase = E + (size_t)(bx * BN) * ISIZE;

    for (int k0 = 0; k0 < ISIZE; k0 += BK) {
        #pragma unroll
        for (int h = 0; h < 2; h++) {
            int r = lrow + h * 64;
            float4 a = *(const float4*)(Abase + (size_t)r * ISIZE + k0 + lcol4);
            As[lcol4 + 0][r] = a.x; As[lcol4 + 1][r] = a.y;
            As[lcol4 + 2][r] = a.z; As[lcol4 + 3][r] = a.w;
            float4 b = *(const float4*)(Bbase + (size_t)r * ISIZE + k0 + lcol4);
            Bs[lcol4 + 0][r] = b.x; Bs[lcol4 + 1][r] = b.y;
            Bs[lcol4 + 2][r] = b.z; Bs[lcol4 + 3][r] = b.w;
        }
        __syncthreads();

        #pragma unroll
        for (int k = 0; k < BK; k++) {
            float ar[8], br[8];
            #pragma unroll
            for (int i = 0; i < 8; i++) ar[i] = As[k][ty * 8 + i];
            #pragma unroll
            for (int j = 0; j < 8; j++) br[j] = Bs[k][tx * 8 + j];
            #pragma unroll
            for (int i = 0; i < 8; i++)
                #pragma unroll
                for (int j = 0; j < 8; j++) acc[i][j] = fmaf(ar[i], br[j], acc[i][j]);
        }
        __syncthreads();
    }

    float* Crow = C + (size_t)(by * BM) * N + bx * BN;
    #pragma unroll
    for (int i = 0; i < 8; i++) {
        float* p = Crow + (size_t)(ty * 8 + i) * N + tx * 8;
        float4* q = (float4*)p;
        q[0] = make_float4(acc[i][0], acc[i][1], acc[i][2], acc[i][3]);
        q[1] = make_float4(acc[i][4], acc[i][5], acc[i][6], acc[i][7]);
    }
}

// ---------------------------------------------------------------------------
// Kernel 3: per-row top-31 mask + relu, in place on C.
// One block (256 threads) per row. Exact 3-pass radix select over monotone
// float keys; exact tie handling (keep lowest indices among equal keys).
// ---------------------------------------------------------------------------
__device__ __forceinline__ unsigned f2key(float f) {
    unsigned u = __float_as_uint(f);
    return (u & 0x80000000u) ? ~u : (u | 0x80000000u);
}
__device__ __forceinline__ float key2f(unsigned k) {
    unsigned u = (k & 0x80000000u) ? (k & 0x7FFFFFFFu) : ~k;
    return __uint_as_float(u);
}

__global__ void __launch_bounds__(256) k_topk(float* __restrict__ C) {
    __shared__ unsigned keys[N];      // 32 KB
    __shared__ unsigned hist[2048];   // 8 KB
    __shared__ unsigned tsum[256];    // 1 KB
    __shared__ unsigned sh_prefix, sh_need, sh_eq;

    int row = blockIdx.x;
    int t = threadIdx.x;
    float* rp = C + (size_t)row * N;

    for (int i = t; i < N; i += 256) keys[i] = f2key(rp[i]);
    __syncthreads();

    unsigned prefix = 0, pmask = 0, need = KTOP;
    const int shifts[3] = {21, 10, 0};
    const int widths[3] = {11, 11, 10};

    for (int p = 0; p < 3; p++) {
        const int shift = shifts[p];
        const unsigned bins = 1u << widths[p];
        const unsigned bmask = bins - 1u;

        for (int i = t; i < 2048; i += 256) hist[i] = 0;
        __syncthreads();

        for (int i = t; i < N; i += 256) {
            unsigned k2 = keys[i];
            if ((k2 & pmask) == prefix) atomicAdd(&hist[(k2 >> shift) & bmask], 1u);
        }
        __syncthreads();

        // each thread sums its group, groups ordered from TOP bin down
        const int g = (int)(bins / 256u);
        unsigned s = 0;
        int hi = (int)bins - 1 - t * g;
        for (int j = 0; j < g; j++) s += hist[hi - j];
        tsum[t] = s;
        __syncthreads();
        // inclusive prefix scan over thread-order (t=0 is topmost group)
        for (int off = 1; off < 256; off <<= 1) {
            unsigned x = (t >= off) ? tsum[t - off] : 0u;
            __syncthreads();
            tsum[t] += x;
            __syncthreads();
        }
        unsigned inc = tsum[t];
        unsigned prev = (t == 0) ? 0u : tsum[t - 1];
        if (inc >= need && prev < need) {
            unsigned cum = prev;
            for (int j = 0; j < g; j++) {
                int b = hi - j;
                unsigned c = hist[b];
                if (cum + c >= need) {
                    sh_prefix = prefix | ((unsigned)b << shift);
                    sh_need = need - cum;
                    break;
                }
                cum += c;
            }
        }
        __syncthreads();
        prefix = sh_prefix;
        need = sh_need;
        pmask |= (bmask << shift);
        __syncthreads();
    }

    const unsigned thr = prefix;     // exact key of 31st largest
    const unsigned quota = need;     // how many equal-to-thr keys to KEEP (lowest index first)

    // count equals
    if (t == 0) sh_eq = 0;
    __syncthreads();
    unsigned myeq = 0;
    for (int i = t; i < N; i += 256) myeq += (keys[i] == thr);
    if (myeq) atomicAdd(&sh_eq, myeq);
    __syncthreads();

    if (sh_eq != quota) {
        // rare duplicate-key case: drop excess equals in index order
        if (t == 0) {
            unsigned c = 0;
            for (int i = 0; i < N; i++) {
                if (keys[i] == thr) {
                    if (c >= quota) keys[i] = 0u;  // demote below threshold
                    c++;
                }
            }
        }
        __syncthreads();
    }

    for (int i = t; i < N; i += 256) {
        unsigned k2 = keys[i];
        float o = 0.0f;
        if (k2 >= thr) o = fmaxf(key2f(k2), 0.0f);
        rp[i] = o;
    }
}

// ---------------------------------------------------------------------------
// launch
// ---------------------------------------------------------------------------
extern "C" void kernel_launch(void* const* d_in, const int* in_sizes, int n_in,
                              void* d_out, int out_size) {
    const float* features = (const float*)d_in[0];  // [N, ISIZE] f32
    const float* w        = (const float*)d_in[1];  // [2, ISIZE] f32
    // d_in[2] = edge_ori (unused by reference)
    float* out = (float*)d_out;                     // [N, N] f32

    float* e;
    cudaGetSymbolAddress((void**)&e, g_e);

    k_normalize<<<N, 256>>>(features, w, e);

    dim3 grid(N / BN, N / BM);
    k_gemm<<<grid, 256>>>(e, out);

    k_topk<<<N, 256>>>(out);
}

// round 5
// speedup vs baseline: 1.9262x; 1.9262x over previous
#include <cuda_runtime.h>
#include <cuda_fp16.h>
#include <stdint.h>

#define N 8192
#define ISIZE 256
#define KTOP 31
#define KCAT 512
#define INV_SCALE2 (1.0f / (1024.0f * 1024.0f))
#define NCHUNK 12
#define TAU 3e-5f
#define CANDMAX 256

#define NTILE 64
#define NBLK (NTILE * (NTILE + 1) / 2)
#define STAGE_BYTES 32768
#define GEMM_SMEM (3 * STAGE_BYTES)

__device__ __align__(16) __half g_E[N * KCAT];
__device__ __align__(16) float  g_Ef[N * ISIZE];

#define SMEM_SWIZZLE_128B(o) ((o) ^ (((o) >> 3) & 0x70))

__device__ __forceinline__ uint32_t smem_to_u32(const void* p) {
    uint32_t a;
    asm("{ .reg .u64 t; cvta.to.shared.u64 t, %1; cvt.u32.u64 %0, t; }" : "=r"(a) : "l"(p));
    return a;
}
__device__ __forceinline__ void ldsm_x4(uint32_t* r, uint32_t addr) {
    asm volatile("ldmatrix.sync.aligned.m8n8.x4.shared.b16 {%0,%1,%2,%3}, [%4];"
                 : "=r"(r[0]), "=r"(r[1]), "=r"(r[2]), "=r"(r[3]) : "r"(addr));
}
__device__ __forceinline__ void mma16816(float* d, const uint32_t* a, const uint32_t* b) {
    asm volatile(
        "mma.sync.aligned.m16n8k16.row.col.f32.f16.f16.f32 "
        "{%0,%1,%2,%3}, {%4,%5,%6,%7}, {%8,%9}, {%0,%1,%2,%3};"
        : "+f"(d[0]), "+f"(d[1]), "+f"(d[2]), "+f"(d[3])
        : "r"(a[0]), "r"(a[1]), "r"(a[2]), "r"(a[3]), "r"(b[0]), "r"(b[1]));
}
#define CP_ASYNC16(dst, src) \
    asm volatile("cp.async.cg.shared.global [%0], [%1], 16;" :: "r"(dst), "l"(src) : "memory")
#define CP_COMMIT() asm volatile("cp.async.commit_group;" ::: "memory")
#define CP_WAIT1()  asm volatile("cp.async.wait_group 1;" ::: "memory")

__device__ __forceinline__ int chunk_col(int c, int is_b) {
    int base = (c & 3) * 64;
    int use_m = is_b ? (c >= 4 && c < 8) : (c >= 8);
    return base + (use_m ? 256 : 0);
}

__global__ void k_normalize(const float* __restrict__ f, const float* __restrict__ w,
                            __half* __restrict__ Ecat, float* __restrict__ Ef) {
    int row = blockIdx.x;
    int t = threadIdx.x;
    float v = f[row * ISIZE + t];
    v = fmaxf(v * w[t], 0.0f) * w[ISIZE + t];

    float s = v * v;
    #pragma unroll
    for (int o = 16; o; o >>= 1) s += __shfl_xor_sync(0xFFFFFFFFu, s, o);
    __shared__ float ws[8];
    if ((t & 31) == 0) ws[t >> 5] = s;
    __syncthreads();
    if (t < 8) {
        float x = ws[t];
        #pragma unroll
        for (int o = 4; o; o >>= 1) x += __shfl_xor_sync(0xFFu, x, o);
        if (t == 0) ws[0] = x;
    }
    __syncthreads();
    float inv = 1.0f / fmaxf(sqrtf(ws[0]), 1e-12f);
    float e = v * inv;                 // EXACT round-1 expression
    Ef[(size_t)row * ISIZE + t] = e;
    float e1024 = e * 1024.0f;
    __half h = __float2half_rn(e1024);
    float m = e1024 - __half2float(h);
    Ecat[(size_t)row * KCAT + t] = h;
    Ecat[(size_t)row * KCAT + ISIZE + t] = __float2half_rn(m);
}

__global__ void __launch_bounds__(256, 1) k_gemm_mma(const __half* __restrict__ E,
                                                     float* __restrict__ C) {
    extern __shared__ char smem[];
    uint32_t sb = smem_to_u32(smem);
    int tid = threadIdx.x;
    int lane = tid & 31, wid = tid >> 5;
    int wm = wid >> 2, wn = wid & 3;

    int b = blockIdx.x;
    int ti = (int)((sqrtf(8.0f * (float)b + 1.0f) - 1.0f) * 0.5f);
    while ((ti + 1) * (ti + 2) / 2 <= b) ti++;
    while (ti * (ti + 1) / 2 > b) ti--;
    int tj = b - ti * (ti + 1) / 2;
    int m0 = ti * 128, n0 = tj * 128;

    float acc[4][4][4];
    #pragma unroll
    for (int i = 0; i < 4; i++)
        #pragma unroll
        for (int j = 0; j < 4; j++)
            #pragma unroll
            for (int q = 0; q < 4; q++) acc[i][j][q] = 0.0f;

    int half_sel = tid >> 7;
    int tl = tid & 127;
    const __half* src_base = E + (size_t)(half_sel ? n0 : m0) * KCAT;
    uint32_t dst_half = (uint32_t)half_sel * 16384u;

    #pragma unroll
    for (int c = 0; c < 2; c++) {
        uint32_t bo = sb + (uint32_t)c * STAGE_BYTES + dst_half;
        const __half* s = src_base + chunk_col(c, half_sel);
        #pragma unroll
        for (int i = 0; i < 8; i++) {
            int idx = i * 128 + tl;
            int r = idx >> 3, cg = idx & 7;
            CP_ASYNC16(bo + SMEM_SWIZZLE_128B((uint32_t)(r * 128 + cg * 16)),
                       s + (size_t)r * KCAT + cg * 8);
        }
        CP_COMMIT();
    }
    CP_WAIT1();
    __syncthreads();

    #pragma unroll 1
    for (int c = 0; c < NCHUNK; c++) {
        if (c + 2 < NCHUNK) {
            uint32_t bo = sb + (uint32_t)((c + 2) % 3) * STAGE_BYTES + dst_half;
            const __half* s = src_base + chunk_col(c + 2, half_sel);
            #pragma unroll
            for (int i = 0; i < 8; i++) {
                int idx = i * 128 + tl;
                int r = idx >> 3, cg = idx & 7;
                CP_ASYNC16(bo + SMEM_SWIZZLE_128B((uint32_t)(r * 128 + cg * 16)),
                           s + (size_t)r * KCAT + cg * 8);
            }
        }
        CP_COMMIT();

        uint32_t Ab = sb + (uint32_t)(c % 3) * STAGE_BYTES;
        uint32_t Bb = Ab + 16384u;
        #pragma unroll
        for (int kk = 0; kk < 4; kk++) {
            uint32_t afr[4][4], bfr[4][2];
            #pragma unroll
            for (int mt = 0; mt < 4; mt++) {
                int row = wm * 64 + mt * 16 + (lane & 15);
                int colb = (kk * 16 + ((lane >> 4) & 1) * 8) * 2;
                ldsm_x4(afr[mt], Ab + SMEM_SWIZZLE_128B((uint32_t)(row * 128 + colb)));
            }
            #pragma unroll
            for (int ntp = 0; ntp < 2; ntp++) {
                uint32_t r4[4];
                int row = wn * 32 + ntp * 16 + (lane & 15);
                int colb = (kk * 16 + ((lane >> 4) & 1) * 8) * 2;
                ldsm_x4(r4, Bb + SMEM_SWIZZLE_128B((uint32_t)(row * 128 + colb)));
                bfr[2 * ntp][0] = r4[0]; bfr[2 * ntp][1] = r4[2];
                bfr[2 * ntp + 1][0] = r4[1]; bfr[2 * ntp + 1][1] = r4[3];
            }
            #pragma unroll
            for (int mt = 0; mt < 4; mt++)
                #pragma unroll
                for (int nt = 0; nt < 4; nt++) mma16816(acc[mt][nt], afr[mt], bfr[nt]);
        }
        CP_WAIT1();
        __syncthreads();
    }

    float* stage = (float*)smem;
    #pragma unroll
    for (int mt = 0; mt < 4; mt++) {
        int r0 = wm * 64 + mt * 16 + (lane >> 2);
        #pragma unroll
        for (int nt = 0; nt < 4; nt++) {
            int c0 = wn * 32 + nt * 8 + (lane & 3) * 2;
            stage[r0 * 132 + c0]           = acc[mt][nt][0] * INV_SCALE2;
            stage[r0 * 132 + c0 + 1]       = acc[mt][nt][1] * INV_SCALE2;
            stage[(r0 + 8) * 132 + c0]     = acc[mt][nt][2] * INV_SCALE2;
            stage[(r0 + 8) * 132 + c0 + 1] = acc[mt][nt][3] * INV_SCALE2;
        }
    }
    __syncthreads();

    #pragma unroll
    for (int it = 0; it < 16; it++) {
        int idx = tid + 256 * it;
        int r = idx >> 5, q = idx & 31;
        float4 v = *(float4*)&stage[r * 132 + q * 4];
        *(float4*)&C[(size_t)(m0 + r) * N + n0 + q * 4] = v;
    }
    if (ti != tj) {
        #pragma unroll
        for (int it = 0; it < 16; it++) {
            int idx = tid + 256 * it;
            int r = idx >> 5, q = idx & 31;
            float4 v;
            v.x = stage[(q * 4 + 0) * 132 + r];
            v.y = stage[(q * 4 + 1) * 132 + r];
            v.z = stage[(q * 4 + 2) * 132 + r];
            v.w = stage[(q * 4 + 3) * 132 + r];
            *(float4*)&C[(size_t)(n0 + r) * N + m0 + q * 4] = v;
        }
    }
}

__device__ __forceinline__ unsigned f2key(float f) {
    unsigned u = __float_as_uint(f);
    return (u & 0x80000000u) ? ~u : (u | 0x80000000u);
}
__device__ __forceinline__ float key2f(unsigned k) {
    unsigned u = (k & 0x80000000u) ? (k & 0x7FFFFFFFu) : ~k;
    return __uint_as_float(u);
}

__global__ void __launch_bounds__(256) k_topk(float* __restrict__ C,
                                              const float* __restrict__ Ef) {
    __shared__ unsigned keys[N];
    __shared__ unsigned hist[2048];
    __shared__ float ei[ISIZE];
    __shared__ int   cand[CANDMAX];
    __shared__ float cdv[CANDMAX];
    __shared__ unsigned char ckeep[CANDMAX];
    __shared__ unsigned wtot[8];
    __shared__ unsigned sh_prefix, sh_need;
    __shared__ int sh_cnt;

    int row = blockIdx.x;
    int t = threadIdx.x;
    float* rp = C + (size_t)row * N;

    for (int i = t; i < N / 4; i += 256) {
        float4 v = ((const float4*)rp)[i];
        uint4 k;
        k.x = f2key(v.x); k.y = f2key(v.y); k.z = f2key(v.z); k.w = f2key(v.w);
        ((uint4*)keys)[i] = k;
    }
    __syncthreads();

    unsigned prefix = 0, pmask = 0, need = KTOP;
    const int shifts[3] = {21, 10, 0};
    const int widths[3] = {11, 11, 10};

    #pragma unroll 1
    for (int p = 0; p < 3; p++) {
        const int shift = shifts[p];
        const unsigned bins = 1u << widths[p];
        const unsigned bmask = bins - 1u;

        for (int i = t; i < 2048; i += 256) hist[i] = 0;
        __syncthreads();
        for (int i = t; i < N; i += 256) {
            unsigned k2 = keys[i];
            if ((k2 & pmask) == prefix) atomicAdd(&hist[(k2 >> shift) & bmask], 1u);
        }
        __syncthreads();

        const int g = (int)(bins / 256u);
        unsigned s = 0;
        int hi = (int)bins - 1 - t * g;
        for (int j = 0; j < g; j++) s += hist[hi - j];
        unsigned v = s;
        #pragma unroll
        for (int o = 1; o < 32; o <<= 1) {
            unsigned x = __shfl_up_sync(0xFFFFFFFFu, v, o);
            if ((t & 31) >= o) v += x;
        }
        if ((t & 31) == 31) wtot[t >> 5] = v;
        __syncthreads();
        if (t < 8) {
            unsigned x = wtot[t];
            #pragma unroll
            for (int o = 1; o < 8; o <<= 1) {
                unsigned y = __shfl_up_sync(0xFFu, x, o);
                if (t >= o) x += y;
            }
            wtot[t] = x;
        }
        __syncthreads();
        unsigned inc = v + ((t >= 32) ? wtot[(t >> 5) - 1] : 0u);
        unsigned prev = inc - s;
        if (inc >= need && prev < need) {
            unsigned cum = prev;
            for (int j = 0; j < g; j++) {
                int bb = hi - j;
                unsigned cnt = hist[bb];
                if (cum + cnt >= need) {
                    sh_prefix = prefix | ((unsigned)bb << shift);
                    sh_need = need - cum;
                    break;
                }
                cum += cnt;
            }
        }
        __syncthreads();
        prefix = sh_prefix;
        need = sh_need;
        pmask |= (bmask << shift);
        __syncthreads();
    }

    const unsigned thr = prefix;
    const float v31 = key2f(thr);
    const unsigned keylo = f2key(v31 - TAU);

    if (t == 0) sh_cnt = 0;
    __syncthreads();
    for (int i = t; i < N; i += 256) {
        if (keys[i] >= keylo) {
            int p = atomicAdd(&sh_cnt, 1);
            if (p < CANDMAX) cand[p] = i;
        }
    }
    __syncthreads();
    int Ccnt = sh_cnt;

    if (Ccnt == KTOP) {
        for (int i = t; i < N / 4; i += 256) {
            uint4 k = ((uint4*)keys)[i];
            float4 o;
            o.x = (k.x >= thr) ? fmaxf(key2f(k.x), 0.0f) : 0.0f;
            o.y = (k.y >= thr) ? fmaxf(key2f(k.y), 0.0f) : 0.0f;
            o.z = (k.z >= thr) ? fmaxf(key2f(k.z), 0.0f) : 0.0f;
            o.w = (k.w >= thr) ? fmaxf(key2f(k.w), 0.0f) : 0.0f;
            ((float4*)rp)[i] = o;
        }
        return;
    }

    if (Ccnt <= CANDMAX) {
        for (int i = t; i < ISIZE; i += 256) ei[i] = Ef[(size_t)row * ISIZE + i];
        __syncthreads();
        if (t < Ccnt) {
            const float* ej = Ef + (size_t)cand[t] * ISIZE;
            float acc = 0.0f;
            #pragma unroll 8
            for (int k = 0; k < ISIZE; k++) acc = fmaf(ei[k], __ldg(&ej[k]), acc);
            cdv[t] = acc;
        }
        __syncthreads();
        if (t < Ccnt) {
            float dv = cdv[t];
            int idx = cand[t];
            int rank = 0;
            for (int s2 = 0; s2 < Ccnt; s2++) {
                float ds = cdv[s2];
                if (ds > dv || (ds == dv && cand[s2] < idx)) rank++;
            }
            ckeep[t] = (rank < KTOP) ? 1 : 0;
        }
        __syncthreads();
        float4 z = make_float4(0.0f, 0.0f, 0.0f, 0.0f);
        for (int i = t; i < N / 4; i += 256) ((float4*)rp)[i] = z;
        __syncthreads();
        if (t < Ccnt && ckeep[t]) rp[cand[t]] = fmaxf(key2f(keys[cand[t]]), 0.0f);
        return;
    }

    if (t == 0) {
        unsigned quota = need;
        unsigned cidx = 0;
        for (int i = 0; i < N; i++) {
            if (keys[i] == thr) {
                if (cidx >= quota) keys[i] = 0u;
                cidx++;
            }
        }
    }
    __syncthreads();
    for (int i = t; i < N; i += 256) {
        unsigned k2 = keys[i];
        rp[i] = (k2 >= thr) ? fmaxf(key2f(k2), 0.0f) : 0.0f;
    }
}

extern "C" void kernel_launch(void* const* d_in, const int* in_sizes, int n_in,
                              void* d_out, int out_size) {
    const float* features = (const float*)d_in[0];
    const float* w        = (const float*)d_in[1];
    float* out = (float*)d_out;

    __half* ecat;
    float* ef;
    cudaGetSymbolAddress((void**)&ecat, g_E);
    cudaGetSymbolAddress((void**)&ef, g_Ef);

    cudaFuncSetAttribute(k_gemm_mma, cudaFuncAttributeMaxDynamicSharedMemorySize, GEMM_SMEM);

    k_normalize<<<N, 256>>>(features, w, ecat, ef);
    k_gemm_mma<<<NBLK, 256, GEMM_SMEM>>>(ecat, out);
    k_topk<<<N, 256>>>(out, ef);
}

// round 6
// speedup vs baseline: 2.1214x; 1.1013x over previous
#include <cuda_runtime.h>
#include <cuda_fp16.h>
#include <stdint.h>

#define N 8192
#define ISIZE 256
#define KTOP 31
#define KCAT 512
#define INV_SCALE2 (1.0f / (1024.0f * 1024.0f))
#define NCHUNK 12
#define TAU 3e-5f
#define CANDMAX 256

#define NTILE 64
#define NBLK (NTILE * (NTILE + 1) / 2)
#define STAGE_BYTES 32768
#define GEMM_SMEM (3 * STAGE_BYTES)

#define TKT 512   // topk threads per block

__device__ __align__(16) __half g_E[N * KCAT];
__device__ __align__(16) float  g_Ef[N * ISIZE];

#define SMEM_SWIZZLE_128B(o) ((o) ^ (((o) >> 3) & 0x70))

__device__ __forceinline__ uint32_t smem_to_u32(const void* p) {
    uint32_t a;
    asm("{ .reg .u64 t; cvta.to.shared.u64 t, %1; cvt.u32.u64 %0, t; }" : "=r"(a) : "l"(p));
    return a;
}
__device__ __forceinline__ void ldsm_x4(uint32_t* r, uint32_t addr) {
    asm volatile("ldmatrix.sync.aligned.m8n8.x4.shared.b16 {%0,%1,%2,%3}, [%4];"
                 : "=r"(r[0]), "=r"(r[1]), "=r"(r[2]), "=r"(r[3]) : "r"(addr));
}
__device__ __forceinline__ void mma16816(float* d, const uint32_t* a, const uint32_t* b) {
    asm volatile(
        "mma.sync.aligned.m16n8k16.row.col.f32.f16.f16.f32 "
        "{%0,%1,%2,%3}, {%4,%5,%6,%7}, {%8,%9}, {%0,%1,%2,%3};"
        : "+f"(d[0]), "+f"(d[1]), "+f"(d[2]), "+f"(d[3])
        : "r"(a[0]), "r"(a[1]), "r"(a[2]), "r"(a[3]), "r"(b[0]), "r"(b[1]));
}
#define CP_ASYNC16(dst, src) \
    asm volatile("cp.async.cg.shared.global [%0], [%1], 16;" :: "r"(dst), "l"(src) : "memory")
#define CP_COMMIT() asm volatile("cp.async.commit_group;" ::: "memory")
#define CP_WAIT1()  asm volatile("cp.async.wait_group 1;" ::: "memory")

__device__ __forceinline__ int chunk_col(int c, int is_b) {
    int base = (c & 3) * 64;
    int use_m = is_b ? (c >= 4 && c < 8) : (c >= 8);
    return base + (use_m ? 256 : 0);
}

// ---------------------------------------------------------------------------
// Kernel 1: normalize + exact fp32 store + fp16 split
// ---------------------------------------------------------------------------
__global__ void k_normalize(const float* __restrict__ f, const float* __restrict__ w,
                            __half* __restrict__ Ecat, float* __restrict__ Ef) {
    int row = blockIdx.x;
    int t = threadIdx.x;
    float v = f[row * ISIZE + t];
    v = fmaxf(v * w[t], 0.0f) * w[ISIZE + t];

    float s = v * v;
    #pragma unroll
    for (int o = 16; o; o >>= 1) s += __shfl_xor_sync(0xFFFFFFFFu, s, o);
    __shared__ float ws[8];
    if ((t & 31) == 0) ws[t >> 5] = s;
    __syncthreads();
    if (t < 8) {
        float x = ws[t];
        #pragma unroll
        for (int o = 4; o; o >>= 1) x += __shfl_xor_sync(0xFFu, x, o);
        if (t == 0) ws[0] = x;
    }
    __syncthreads();
    float inv = 1.0f / fmaxf(sqrtf(ws[0]), 1e-12f);
    float e = v * inv;                 // EXACT round-1 expression
    Ef[(size_t)row * ISIZE + t] = e;
    float e1024 = e * 1024.0f;
    __half h = __float2half_rn(e1024);
    float m = e1024 - __half2float(h);
    Ecat[(size_t)row * KCAT + t] = h;
    Ecat[(size_t)row * KCAT + ISIZE + t] = __float2half_rn(m);
}

// ---------------------------------------------------------------------------
// Kernel 2: C = (H*H^T + H*M^T + M*H^T)/2^20 via HMMA; occupancy 2
// ---------------------------------------------------------------------------
__global__ void __launch_bounds__(256, 2) k_gemm_mma(const __half* __restrict__ E,
                                                     float* __restrict__ C) {
    extern __shared__ char smem[];
    uint32_t sb = smem_to_u32(smem);
    int tid = threadIdx.x;
    int lane = tid & 31, wid = tid >> 5;
    int wm = wid >> 2, wn = wid & 3;

    int b = blockIdx.x;
    int ti = (int)((sqrtf(8.0f * (float)b + 1.0f) - 1.0f) * 0.5f);
    while ((ti + 1) * (ti + 2) / 2 <= b) ti++;
    while (ti * (ti + 1) / 2 > b) ti--;
    int tj = b - ti * (ti + 1) / 2;
    int m0 = ti * 128, n0 = tj * 128;

    float acc[4][4][4];
    #pragma unroll
    for (int i = 0; i < 4; i++)
        #pragma unroll
        for (int j = 0; j < 4; j++)
            #pragma unroll
            for (int q = 0; q < 4; q++) acc[i][j][q] = 0.0f;

    int half_sel = tid >> 7;
    int tl = tid & 127;
    const __half* src_base = E + (size_t)(half_sel ? n0 : m0) * KCAT;
    uint32_t dst_half = (uint32_t)half_sel * 16384u;

    #pragma unroll
    for (int c = 0; c < 2; c++) {
        uint32_t bo = sb + (uint32_t)c * STAGE_BYTES + dst_half;
        const __half* s = src_base + chunk_col(c, half_sel);
        #pragma unroll
        for (int i = 0; i < 8; i++) {
            int idx = i * 128 + tl;
            int r = idx >> 3, cg = idx & 7;
            CP_ASYNC16(bo + SMEM_SWIZZLE_128B((uint32_t)(r * 128 + cg * 16)),
                       s + (size_t)r * KCAT + cg * 8);
        }
        CP_COMMIT();
    }
    CP_WAIT1();
    __syncthreads();

    #pragma unroll 1
    for (int c = 0; c < NCHUNK; c++) {
        if (c + 2 < NCHUNK) {
            uint32_t bo = sb + (uint32_t)((c + 2) % 3) * STAGE_BYTES + dst_half;
            const __half* s = src_base + chunk_col(c + 2, half_sel);
            #pragma unroll
            for (int i = 0; i < 8; i++) {
                int idx = i * 128 + tl;
                int r = idx >> 3, cg = idx & 7;
                CP_ASYNC16(bo + SMEM_SWIZZLE_128B((uint32_t)(r * 128 + cg * 16)),
                           s + (size_t)r * KCAT + cg * 8);
            }
        }
        CP_COMMIT();

        uint32_t Ab = sb + (uint32_t)(c % 3) * STAGE_BYTES;
        uint32_t Bb = Ab + 16384u;
        #pragma unroll
        for (int kk = 0; kk < 4; kk++) {
            uint32_t afr[4][4], bfr[4][2];
            #pragma unroll
            for (int mt = 0; mt < 4; mt++) {
                int row = wm * 64 + mt * 16 + (lane & 15);
                int colb = (kk * 16 + ((lane >> 4) & 1) * 8) * 2;
                ldsm_x4(afr[mt], Ab + SMEM_SWIZZLE_128B((uint32_t)(row * 128 + colb)));
            }
            #pragma unroll
            for (int ntp = 0; ntp < 2; ntp++) {
                uint32_t r4[4];
                int row = wn * 32 + ntp * 16 + (lane & 15);
                int colb = (kk * 16 + ((lane >> 4) & 1) * 8) * 2;
                ldsm_x4(r4, Bb + SMEM_SWIZZLE_128B((uint32_t)(row * 128 + colb)));
                bfr[2 * ntp][0] = r4[0]; bfr[2 * ntp][1] = r4[2];
                bfr[2 * ntp + 1][0] = r4[1]; bfr[2 * ntp + 1][1] = r4[3];
            }
            #pragma unroll
            for (int mt = 0; mt < 4; mt++)
                #pragma unroll
                for (int nt = 0; nt < 4; nt++) mma16816(acc[mt][nt], afr[mt], bfr[nt]);
        }
        CP_WAIT1();
        __syncthreads();
    }

    float* stage = (float*)smem;
    #pragma unroll
    for (int mt = 0; mt < 4; mt++) {
        int r0 = wm * 64 + mt * 16 + (lane >> 2);
        #pragma unroll
        for (int nt = 0; nt < 4; nt++) {
            int c0 = wn * 32 + nt * 8 + (lane & 3) * 2;
            stage[r0 * 132 + c0]           = acc[mt][nt][0] * INV_SCALE2;
            stage[r0 * 132 + c0 + 1]       = acc[mt][nt][1] * INV_SCALE2;
            stage[(r0 + 8) * 132 + c0]     = acc[mt][nt][2] * INV_SCALE2;
            stage[(r0 + 8) * 132 + c0 + 1] = acc[mt][nt][3] * INV_SCALE2;
        }
    }
    __syncthreads();

    #pragma unroll
    for (int it = 0; it < 16; it++) {
        int idx = tid + 256 * it;
        int r = idx >> 5, q = idx & 31;
        float4 v = *(float4*)&stage[r * 132 + q * 4];
        __stcs((float4*)&C[(size_t)(m0 + r) * N + n0 + q * 4], v);
    }
    if (ti != tj) {
        #pragma unroll
        for (int it = 0; it < 16; it++) {
            int idx = tid + 256 * it;
            int r = idx >> 5, q = idx & 31;
            float4 v;
            v.x = stage[(q * 4 + 0) * 132 + r];
            v.y = stage[(q * 4 + 1) * 132 + r];
            v.z = stage[(q * 4 + 2) * 132 + r];
            v.w = stage[(q * 4 + 3) * 132 + r];
            __stcs((float4*)&C[(size_t)(n0 + r) * N + m0 + q * 4], v);
        }
    }
}

// ---------------------------------------------------------------------------
// Kernel 3: per-row top-31 + relu; 512 threads; borderline rows verified
// with exact round-1 fp32 dots.
// ---------------------------------------------------------------------------
__device__ __forceinline__ unsigned f2key(float f) {
    unsigned u = __float_as_uint(f);
    return (u & 0x80000000u) ? ~u : (u | 0x80000000u);
}
__device__ __forceinline__ float key2f(unsigned k) {
    unsigned u = (k & 0x80000000u) ? (k & 0x7FFFFFFFu) : ~k;
    return __uint_as_float(u);
}

__global__ void __launch_bounds__(TKT) k_topk(float* __restrict__ C,
                                              const float* __restrict__ Ef) {
    __shared__ unsigned keys[N];
    __shared__ unsigned hist[2048];
    __shared__ float ei[ISIZE];
    __shared__ int   cand[CANDMAX];
    __shared__ float cdv[CANDMAX];
    __shared__ unsigned char ckeep[CANDMAX];
    __shared__ unsigned wtot[TKT / 32];
    __shared__ unsigned sh_prefix, sh_need;
    __shared__ int sh_cnt;

    int row = blockIdx.x;
    int t = threadIdx.x;
    float* rp = C + (size_t)row * N;

    for (int i = t; i < N / 4; i += TKT) {
        float4 v = __ldcs((const float4*)rp + i);
        uint4 k;
        k.x = f2key(v.x); k.y = f2key(v.y); k.z = f2key(v.z); k.w = f2key(v.w);
        ((uint4*)keys)[i] = k;
    }
    __syncthreads();

    unsigned prefix = 0, pmask = 0, need = KTOP;
    const int shifts[3] = {21, 10, 0};
    const int widths[3] = {11, 11, 10};

    #pragma unroll 1
    for (int p = 0; p < 3; p++) {
        const int shift = shifts[p];
        const unsigned bins = 1u << widths[p];
        const unsigned bmask = bins - 1u;

        for (int i = t; i < 2048; i += TKT) hist[i] = 0;
        __syncthreads();
        for (int i = t; i < N; i += TKT) {
            unsigned k2 = keys[i];
            if ((k2 & pmask) == prefix) atomicAdd(&hist[(k2 >> shift) & bmask], 1u);
        }
        __syncthreads();

        const int g = (int)(bins / TKT);
        unsigned s = 0;
        int hi = (int)bins - 1 - t * g;
        for (int j = 0; j < g; j++) s += hist[hi - j];
        unsigned v = s;
        #pragma unroll
        for (int o = 1; o < 32; o <<= 1) {
            unsigned x = __shfl_up_sync(0xFFFFFFFFu, v, o);
            if ((t & 31) >= o) v += x;
        }
        if ((t & 31) == 31) wtot[t >> 5] = v;
        __syncthreads();
        if (t < TKT / 32) {
            unsigned x = wtot[t];
            #pragma unroll
            for (int o = 1; o < TKT / 32; o <<= 1) {
                unsigned y = __shfl_up_sync((1u << (TKT / 32)) - 1u, x, o);
                if (t >= o) x += y;
            }
            wtot[t] = x;
        }
        __syncthreads();
        unsigned inc = v + ((t >= 32) ? wtot[(t >> 5) - 1] : 0u);
        unsigned prev = inc - s;
        if (inc >= need && prev < need) {
            unsigned cum = prev;
            for (int j = 0; j < g; j++) {
                int bb = hi - j;
                unsigned cnt = hist[bb];
                if (cum + cnt >= need) {
                    sh_prefix = prefix | ((unsigned)bb << shift);
                    sh_need = need - cum;
                    break;
                }
                cum += cnt;
            }
        }
        __syncthreads();
        prefix = sh_prefix;
        need = sh_need;
        pmask |= (bmask << shift);
        __syncthreads();
    }

    const unsigned thr = prefix;
    const float v31 = key2f(thr);
    const unsigned keylo = f2key(v31 - TAU);

    if (t == 0) sh_cnt = 0;
    __syncthreads();
    for (int i = t; i < N; i += TKT) {
        if (keys[i] >= keylo) {
            int p = atomicAdd(&sh_cnt, 1);
            if (p < CANDMAX) cand[p] = i;
        }
    }
    __syncthreads();
    int Ccnt = sh_cnt;

    if (Ccnt == KTOP) {
        for (int i = t; i < N / 4; i += TKT) {
            uint4 k = ((uint4*)keys)[i];
            float4 o;
            o.x = (k.x >= thr) ? fmaxf(key2f(k.x), 0.0f) : 0.0f;
            o.y = (k.y >= thr) ? fmaxf(key2f(k.y), 0.0f) : 0.0f;
            o.z = (k.z >= thr) ? fmaxf(key2f(k.z), 0.0f) : 0.0f;
            o.w = (k.w >= thr) ? fmaxf(key2f(k.w), 0.0f) : 0.0f;
            __stcs((float4*)rp + i, o);
        }
        return;
    }

    if (Ccnt <= CANDMAX) {
        for (int i = t; i < ISIZE; i += TKT) ei[i] = Ef[(size_t)row * ISIZE + i];
        __syncthreads();
        if (t < Ccnt) {
            const float* ej = Ef + (size_t)cand[t] * ISIZE;
            float acc = 0.0f;
            #pragma unroll 8
            for (int k = 0; k < ISIZE; k++) acc = fmaf(ei[k], __ldg(&ej[k]), acc);
            cdv[t] = acc;
        }
        __syncthreads();
        if (t < Ccnt) {
            float dv = cdv[t];
            int idx = cand[t];
            int rank = 0;
            for (int s2 = 0; s2 < Ccnt; s2++) {
                float ds = cdv[s2];
                if (ds > dv || (ds == dv && cand[s2] < idx)) rank++;
            }
            ckeep[t] = (rank < KTOP) ? 1 : 0;
        }
        __syncthreads();
        float4 z = make_float4(0.0f, 0.0f, 0.0f, 0.0f);
        for (int i = t; i < N / 4; i += TKT) __stcs((float4*)rp + i, z);
        __syncthreads();
        if (t < Ccnt && ckeep[t]) rp[cand[t]] = fmaxf(key2f(keys[cand[t]]), 0.0f);
        return;
    }

    if (t == 0) {
        unsigned quota = need;
        unsigned cidx = 0;
        for (int i = 0; i < N; i++) {
            if (keys[i] == thr) {
                if (cidx >= quota) keys[i] = 0u;
                cidx++;
            }
        }
    }
    __syncthreads();
    for (int i = t; i < N; i += TKT) {
        unsigned k2 = keys[i];
        rp[i] = (k2 >= thr) ? fmaxf(key2f(k2), 0.0f) : 0.0f;
    }
}

extern "C" void kernel_launch(void* const* d_in, const int* in_sizes, int n_in,
                              void* d_out, int out_size) {
    const float* features = (const float*)d_in[0];
    const float* w        = (const float*)d_in[1];
    float* out = (float*)d_out;

    __half* ecat;
    float* ef;
    cudaGetSymbolAddress((void**)&ecat, g_E);
    cudaGetSymbolAddress((void**)&ef, g_Ef);

    cudaFuncSetAttribute(k_gemm_mma, cudaFuncAttributeMaxDynamicSharedMemorySize, GEMM_SMEM);

    k_normalize<<<N, 256>>>(features, w, ecat, ef);
    k_gemm_mma<<<NBLK, 256, GEMM_SMEM>>>(ecat, out);
    k_topk<<<N, TKT>>>(out, ef);
}